// round 1
// baseline (speedup 1.0000x reference)
#include <cuda_runtime.h>

// S4D kernel generation:
//   K[h,l] = 2 * Re( sum_n dC[h,n] * dA[h,n]^l ),  h in [0,1024), l in [0,4096), n in [0,32)
// Strategy: complex recurrence w <- w * dA (5 FFMA-class ops per mode-step) instead of
// per-element exp/sincos (MUFU-bound). Chunk starts via repeated squaring (no MUFU
// range-reduction error at large l).

#define HN   1024   // H (d_model)
#define NM   32     // N/2 complex modes
#define LL   4096   // sequence length
#define TPB  64     // threads per block (one block per h)
#define CHUNK (LL / TPB)  // 64 contiguous l's per thread
#define LOG2_TPB 6

__global__ void __launch_bounds__(TPB)
s4d_vandermonde_kernel(const float* __restrict__ log_dt,      // (H)
                       const float* __restrict__ C_real,      // (1,H,NM,2)
                       const float* __restrict__ log_A_real,  // (H,NM)
                       const float* __restrict__ A_imag,      // (H,NM)
                       float* __restrict__ out)               // (1,H,L)
{
    const int h = blockIdx.x;
    const int t = threadIdx.x;

    __shared__ float s_dAr[NM], s_dAi[NM], s_dCr[NM], s_dCi[NM];
    // S[j][n] = dA_n ^ (CHUNK * 2^j), j = 0..LOG2_TPB-1
    __shared__ float s_Sr[LOG2_TPB][NM], s_Si[LOG2_TPB][NM];

    if (t < NM) {
        const int n = t;
        const float dt = expf(log_dt[h]);
        const float Ar = -expf(log_A_real[h * NM + n]);
        const float Ai = A_imag[h * NM + n];
        const float dtAr = Ar * dt;
        const float dtAi = Ai * dt;
        // den = 1 - dtA/2
        const float denr = 1.0f - 0.5f * dtAr;
        const float deni = -0.5f * dtAi;
        const float inv  = 1.0f / (denr * denr + deni * deni);
        // B = dt / den = dt * conj(den) * inv
        const float Br = dt * denr * inv;
        const float Bi = -dt * deni * inv;
        const float Cr = C_real[(h * NM + n) * 2 + 0];
        const float Ci = C_real[(h * NM + n) * 2 + 1];
        // dC = C * B
        s_dCr[n] = Cr * Br - Ci * Bi;
        s_dCi[n] = Cr * Bi + Ci * Br;
        // dA = (1 + dtA/2) / den
        const float numr = 1.0f + 0.5f * dtAr;
        const float numi = 0.5f * dtAi;
        const float dAr = (numr * denr + numi * deni) * inv;
        const float dAi = (numi * denr - numr * deni) * inv;
        s_dAr[n] = dAr;
        s_dAi[n] = dAi;
        // P = dA^CHUNK via 6 squarings (CHUNK = 64 = 2^6)
        float pr = dAr, pi = dAi;
        #pragma unroll
        for (int j = 0; j < 6; ++j) {
            const float nr = pr * pr - pi * pi;
            const float ni = 2.0f * pr * pi;
            pr = nr; pi = ni;
        }
        // Ladder S_j = dA^(CHUNK * 2^j)
        #pragma unroll
        for (int j = 0; j < LOG2_TPB; ++j) {
            s_Sr[j][n] = pr;
            s_Si[j][n] = pi;
            const float nr = pr * pr - pi * pi;
            const float ni = 2.0f * pr * pi;
            pr = nr; pi = ni;
        }
    }
    __syncthreads();

    // Per-thread state: all 32 modes. w_n = dC_n * dA_n^(t*CHUNK)
    float ar[NM], ai[NM], wr[NM], wi[NM];
    #pragma unroll
    for (int n = 0; n < NM; ++n) {
        ar[n] = s_dAr[n];
        ai[n] = s_dAi[n];
        float xr = s_dCr[n];
        float xi = s_dCi[n];
        #pragma unroll
        for (int j = 0; j < LOG2_TPB; ++j) {
            if ((t >> j) & 1) {
                const float sr = s_Sr[j][n];
                const float si = s_Si[j][n];
                const float nr = xr * sr - xi * si;
                const float ni = xr * si + xi * sr;
                xr = nr; xi = ni;
            }
        }
        wr[n] = xr;
        wi[n] = xi;
    }

    float* __restrict__ o = out + (size_t)h * LL + t * CHUNK;

    // Mainloop: per step, emit 2*sum_n Re(w_n), then w_n *= dA_n.
    // 4 steps buffered into a float4 store. 4 partial accumulators break the
    // serial add chain (FFMA lat 4); 32 independent mode recurrences give ILP.
    for (int s = 0; s < CHUNK; s += 4) {
        float res[4];
        #pragma unroll
        for (int q = 0; q < 4; ++q) {
            float a0 = 0.f, a1 = 0.f, a2 = 0.f, a3 = 0.f;
            #pragma unroll
            for (int n = 0; n < NM; n += 4) {
                a0 += wr[n + 0];
                a1 += wr[n + 1];
                a2 += wr[n + 2];
                a3 += wr[n + 3];
            }
            res[q] = 2.0f * ((a0 + a1) + (a2 + a3));
            #pragma unroll
            for (int n = 0; n < NM; ++n) {
                const float nr = wr[n] * ar[n] - wi[n] * ai[n];
                const float ni = wr[n] * ai[n] + wi[n] * ar[n];
                wr[n] = nr;
                wi[n] = ni;
            }
        }
        *reinterpret_cast<float4*>(o + s) = make_float4(res[0], res[1], res[2], res[3]);
    }
}

extern "C" void kernel_launch(void* const* d_in, const int* in_sizes, int n_in,
                              void* d_out, int out_size) {
    const float* log_dt     = (const float*)d_in[0];
    const float* C_real     = (const float*)d_in[1];
    const float* log_A_real = (const float*)d_in[2];
    const float* A_imag     = (const float*)d_in[3];
    // d_in[4] = L (int32, compile-time 4096 here)
    float* out = (float*)d_out;
    s4d_vandermonde_kernel<<<HN, TPB>>>(log_dt, C_real, log_A_real, A_imag, out);
}